// round 2
// baseline (speedup 1.0000x reference)
#include <cuda_runtime.h>
#include <math.h>

#define HW 4096
#define NC 256
#define NB 4

// ---- device scratch (no dynamic allocation allowed) ----
__device__ float g_ch_avg[NB*NC];
__device__ float g_ch_max[NB*NC];
__device__ float g_ch_att[NB*NC];
__device__ float g_sp_avg[NB*HW];
__device__ float g_sp_max[NB*HW];
__device__ float g_s_att[NB*HW];
// attention scratch (only used when gamma != 0; never in this bench)
__device__ float g_q[NB*32*HW];
__device__ float g_k[NB*32*HW];
__device__ float g_v[NB*NC*HW];

// K1: per-(b,c) spatial mean & max over 4096 pixels
__global__ void k_chstats(const float* __restrict__ x) {
    int bc = blockIdx.x;            // 0..1023
    int t  = threadIdx.x;           // 256
    const float4* xr = reinterpret_cast<const float4*>(x + (size_t)bc * HW);
    float s = 0.f, m = -1e30f;
#pragma unroll
    for (int i = 0; i < 4; i++) {
        float4 v = xr[t + i * 256];
        s += v.x + v.y + v.z + v.w;
        m = fmaxf(m, fmaxf(fmaxf(v.x, v.y), fmaxf(v.z, v.w)));
    }
    __shared__ float ss[256], sm[256];
    ss[t] = s; sm[t] = m; __syncthreads();
    for (int o = 128; o > 0; o >>= 1) {
        if (t < o) { ss[t] += ss[t + o]; sm[t] = fmaxf(sm[t], sm[t + o]); }
        __syncthreads();
    }
    if (t == 0) { g_ch_avg[bc] = ss[0] * (1.f / HW); g_ch_max[bc] = sm[0]; }
}

// K2: shared-MLP channel attention. h = relu(avg@W1^T) + relu(max@W1^T); att = sigmoid(h@W2^T)
__global__ void k_mlp(const float* __restrict__ w1, const float* __restrict__ w2) {
    int b = blockIdx.x, t = threadIdx.x;
    __shared__ float sa[256], sx[256], sh[16];
    sa[t] = g_ch_avg[b * 256 + t];
    sx[t] = g_ch_max[b * 256 + t];
    __syncthreads();
    if (t < 16) {
        float ha = 0.f, hm = 0.f;
        const float* wr = w1 + t * 256;
        for (int c = 0; c < 256; c++) { ha += sa[c] * wr[c]; hm += sx[c] * wr[c]; }
        sh[t] = fmaxf(ha, 0.f) + fmaxf(hm, 0.f);
    }
    __syncthreads();
    float o = 0.f;
    const float* w2r = w2 + t * 16;
#pragma unroll
    for (int r = 0; r < 16; r++) o += sh[r] * w2r[r];
    g_ch_att[b * 256 + t] = 1.f / (1.f + expf(-o));
}

// K3: per-pixel channel mean & max of (x * ch_att).
// Block = 64 pixels x 4 channel-groups of 64 channels each.
__global__ void k_spstats(const float* __restrict__ x) {
    int t   = threadIdx.x;
    int px  = t & 63, grp = t >> 6;
    int pid = blockIdx.x * 64 + px;           // 0..16383, block stays in one batch
    int b   = pid >> 12, p = pid & 4095;
    __shared__ float att[256], ssum[256], smx[256];
    att[t] = g_ch_att[(b << 8) + t];
    __syncthreads();
    const float* xb = x + ((size_t)b << 20) + p;
    float s = 0.f, m = -1e30f;
    int cbase = grp << 6;
#pragma unroll 8
    for (int k = 0; k < 64; k++) {
        float v = xb[(size_t)(cbase + k) << 12] * att[cbase + k];
        s += v; m = fmaxf(m, v);
    }
    ssum[t] = s; smx[t] = m; __syncthreads();
    if (grp == 0) {
        float ts = ssum[px] + ssum[px + 64] + ssum[px + 128] + ssum[px + 192];
        float tm = fmaxf(fmaxf(smx[px], smx[px + 64]), fmaxf(smx[px + 128], smx[px + 192]));
        g_sp_avg[pid] = ts * (1.f / 256.f);
        g_sp_max[pid] = tm;
    }
}

// K4: 7x7 conv over [avg_s, max_s] with zero padding, then sigmoid. One block per batch.
__global__ void k_conv(const float* __restrict__ w_sp) {
    int b = blockIdx.x, t = threadIdx.x;
    __shared__ float sa[4096], sx[4096], w[98];
    for (int i = 0; i < 16; i++) {
        sa[t + i * 256] = g_sp_avg[b * 4096 + t + i * 256];
        sx[t + i * 256] = g_sp_max[b * 4096 + t + i * 256];
    }
    if (t < 98) w[t] = w_sp[t];
    __syncthreads();
    for (int i = 0; i < 16; i++) {
        int op = t + i * 256;
        int y = op >> 6, xx = op & 63;
        float acc = 0.f;
#pragma unroll
        for (int ky = 0; ky < 7; ky++) {
            int iy = y + ky - 3;
            if ((unsigned)iy < 64u) {
#pragma unroll
                for (int kx = 0; kx < 7; kx++) {
                    int ix = xx + kx - 3;
                    if ((unsigned)ix < 64u) {
                        acc += w[ky * 7 + kx] * sa[iy * 64 + ix]
                             + w[49 + ky * 7 + kx] * sx[iy * 64 + ix];
                    }
                }
            }
        }
        g_s_att[b * 4096 + op] = 1.f / (1.f + expf(-acc));
    }
}

// K5: out = x * ch_att[b,c] * s_att[b,p]  (this IS the final answer when gamma==0)
__global__ void k_apply(const float* __restrict__ x, float* __restrict__ out) {
    int i4 = blockIdx.x * 256 + threadIdx.x;   // 1,048,576 float4s
    int e  = i4 << 2;
    int b  = e >> 20, c = (e >> 12) & 255, p = e & 4095;
    float a = g_ch_att[(b << 8) + c];
    float4 sv = *reinterpret_cast<const float4*>(&g_s_att[(b << 12) + p]);
    float4 xv = *reinterpret_cast<const float4*>(x + e);
    float4 o;
    o.x = xv.x * a * sv.x; o.y = xv.y * a * sv.y;
    o.z = xv.z * a * sv.z; o.w = xv.w * a * sv.w;
    *reinterpret_cast<float4*>(out + e) = o;
}

// ---- gamma != 0 path (exact; never runs in this bench since gamma == 0) ----

// K6: q/k/v 1x1-conv projections of x2 (= out buffer)
__global__ void k_proj(const float* __restrict__ x2,
                       const float* __restrict__ wq, const float* __restrict__ bq,
                       const float* __restrict__ wk, const float* __restrict__ bk,
                       const float* __restrict__ wv, const float* __restrict__ bv,
                       const float* __restrict__ gamma) {
    if (gamma[0] == 0.f) return;
    int chunk = blockIdx.x, b = blockIdx.y, t = threadIdx.x;
    __shared__ float xs[256 * 32];
    {
        const float* src = x2 + ((size_t)(b * 256 + t)) * HW + chunk * 32;
        for (int p = 0; p < 32; p += 4) {
            float4 v = *reinterpret_cast<const float4*>(src + p);
            xs[t * 32 + p] = v.x; xs[t * 32 + p + 1] = v.y;
            xs[t * 32 + p + 2] = v.z; xs[t * 32 + p + 3] = v.w;
        }
    }
    __syncthreads();
    for (int k = 0; k < 40; k++) {           // 320 outputs * 32 pixels / 256 threads
        int oi = k * 256 + t;
        int o = oi >> 5, p = oi & 31;
        const float* wr; float bias; float* dst; int row;
        if (o < 32)      { wr = wq + o * 256;        bias = bq[o];      dst = g_q; row = b * 32 + o; }
        else if (o < 64) { int r = o - 32; wr = wk + r * 256; bias = bk[r]; dst = g_k; row = b * 32 + r; }
        else             { int r = o - 64; wr = wv + r * 256; bias = bv[r]; dst = g_v; row = b * 256 + r; }
        float acc = bias;
        for (int c = 0; c < 256; c++) acc += wr[c] * xs[c * 32 + p];
        dst[(size_t)row * HW + chunk * 32 + p] = acc;
    }
}

// K7: one block per (b, query i): softmax over j, out[b,c,i] += g * sum_j p_j v[c,j]
__global__ void k_attn(float* __restrict__ out, const float* __restrict__ gamma) {
    float g = gamma[0];
    if (g == 0.f) return;
    int bi = blockIdx.x;
    int b = bi >> 12, i = bi & 4095;
    int t = threadIdx.x;
    __shared__ float qv[32];
    __shared__ float sbuf[4096];
    __shared__ float red[256];
    if (t < 32) qv[t] = g_q[(b * 32 + t) * HW + i];
    __syncthreads();
    float lm = -1e30f;
    for (int j = t; j < 4096; j += 256) {
        float s = 0.f;
#pragma unroll
        for (int d = 0; d < 32; d++) s += qv[d] * g_k[(b * 32 + d) * HW + j];
        sbuf[j] = s; lm = fmaxf(lm, s);
    }
    red[t] = lm; __syncthreads();
    for (int o = 128; o > 0; o >>= 1) {
        if (t < o) red[t] = fmaxf(red[t], red[t + o]);
        __syncthreads();
    }
    float m = red[0]; __syncthreads();
    float ls = 0.f;
    for (int j = t; j < 4096; j += 256) {
        float e = expf(sbuf[j] - m);
        sbuf[j] = e; ls += e;
    }
    red[t] = ls; __syncthreads();
    for (int o = 128; o > 0; o >>= 1) {
        if (t < o) red[t] += red[t + o];
        __syncthreads();
    }
    float inv = 1.f / red[0]; __syncthreads();
    // thread t = channel c
    float acc = 0.f;
    const float* vr = g_v + (size_t)(b * 256 + t) * HW;
    for (int j = 0; j < 4096; j++) acc += vr[j] * sbuf[j];
    out[(b * 256 + t) * HW + i] += g * acc * inv;
}

extern "C" void kernel_launch(void* const* d_in, const int* in_sizes, int n_in,
                              void* d_out, int out_size) {
    const float* x     = (const float*)d_in[0];
    const float* w1    = (const float*)d_in[1];
    const float* w2    = (const float*)d_in[2];
    const float* w_sp  = (const float*)d_in[3];
    const float* wq    = (const float*)d_in[4];
    const float* bq    = (const float*)d_in[5];
    const float* wk    = (const float*)d_in[6];
    const float* bk    = (const float*)d_in[7];
    const float* wv    = (const float*)d_in[8];
    const float* bv    = (const float*)d_in[9];
    const float* gamma = (const float*)d_in[10];
    float* out = (float*)d_out;

    k_chstats<<<NB * NC, 256>>>(x);
    k_mlp<<<NB, 256>>>(w1, w2);
    k_spstats<<<NB * HW / 64, 256>>>(x);
    k_conv<<<NB, 256>>>(w_sp);
    k_apply<<<NB * NC * HW / 1024, 256>>>(x, out);
    // gamma != 0 path: in-device early exit when gamma == 0 (exact identity)
    k_proj<<<dim3(HW / 32, NB), 256>>>(out, wq, bq, wk, bk, wv, bv, gamma);
    k_attn<<<NB * HW, 256>>>(out, gamma);
}

// round 3
// speedup vs baseline: 1.8655x; 1.8655x over previous
#include <cuda_runtime.h>
#include <math.h>

#define HW 4096
#define NC 256
#define NB 4

// ---- device scratch (no dynamic allocation allowed) ----
__device__ float g_ch_avg[NB*NC];
__device__ float g_ch_max[NB*NC];
__device__ float g_ch_att[NB*NC];
__device__ float g_sp_avg[NB*HW];
__device__ float g_sp_max[NB*HW];
__device__ float g_s_att[NB*HW];
// attention scratch (only used when gamma != 0; never in this bench)
__device__ float g_q[NB*32*HW];
__device__ float g_k[NB*32*HW];
__device__ float g_v[NB*NC*HW];

// K1: per-(b,c) spatial mean & max over 4096 pixels
__global__ void k_chstats(const float* __restrict__ x) {
    int bc = blockIdx.x;            // 0..1023
    int t  = threadIdx.x;           // 256
    const float4* xr = reinterpret_cast<const float4*>(x + (size_t)bc * HW);
    float s = 0.f, m = -1e30f;
#pragma unroll
    for (int i = 0; i < 4; i++) {
        float4 v = xr[t + i * 256];
        s += v.x + v.y + v.z + v.w;
        m = fmaxf(m, fmaxf(fmaxf(v.x, v.y), fmaxf(v.z, v.w)));
    }
    __shared__ float ss[256], sm[256];
    ss[t] = s; sm[t] = m; __syncthreads();
    for (int o = 128; o > 0; o >>= 1) {
        if (t < o) { ss[t] += ss[t + o]; sm[t] = fmaxf(sm[t], sm[t + o]); }
        __syncthreads();
    }
    if (t == 0) { g_ch_avg[bc] = ss[0] * (1.f / HW); g_ch_max[bc] = sm[0]; }
}

// K2: shared-MLP channel attention. h = relu(avg@W1^T) + relu(max@W1^T); att = sigmoid(h@W2^T)
// One block per batch; one warp per 2 hidden units (shuffle reduction).
__global__ void k_mlp(const float* __restrict__ w1, const float* __restrict__ w2) {
    int b = blockIdx.x, t = threadIdx.x;
    int wid = t >> 5, lid = t & 31;
    __shared__ float sa[256], sx[256], sh[16];
    sa[t] = g_ch_avg[b * 256 + t];
    sx[t] = g_ch_max[b * 256 + t];
    __syncthreads();
    // 16 hidden units across 8 warps -> 2 units per warp
#pragma unroll
    for (int u = 0; u < 2; u++) {
        int h = wid * 2 + u;
        const float* wr = w1 + h * 256;
        float ha = 0.f, hm = 0.f;
#pragma unroll
        for (int k = 0; k < 8; k++) {
            int c = k * 32 + lid;
            float wv = wr[c];
            ha += sa[c] * wv; hm += sx[c] * wv;
        }
#pragma unroll
        for (int o = 16; o > 0; o >>= 1) {
            ha += __shfl_down_sync(0xffffffff, ha, o);
            hm += __shfl_down_sync(0xffffffff, hm, o);
        }
        if (lid == 0) sh[h] = fmaxf(ha, 0.f) + fmaxf(hm, 0.f);
    }
    __syncthreads();
    float o = 0.f;
    const float* w2r = w2 + t * 16;
#pragma unroll
    for (int r = 0; r < 16; r++) o += sh[r] * w2r[r];
    g_ch_att[b * 256 + t] = 1.f / (1.f + expf(-o));
}

// K3: per-pixel channel mean & max of (x * ch_att).
// Block = 64 four-pixel chunks (256 px) x 4 channel-groups of 64 channels.
__global__ void k_spstats(const float* __restrict__ x) {
    int t   = threadIdx.x;
    int pq  = t & 63, grp = t >> 6;
    int blk = blockIdx.x;               // 64 blocks, 256 px each
    int b   = blk >> 4;
    int p0  = (blk & 15) * 256 + pq * 4;
    __shared__ float att[256];
    __shared__ float4 ssum[256], smx[256];
    att[t] = g_ch_att[(b << 8) + t];
    __syncthreads();
    const float* xb = x + ((size_t)b << 20) + p0;
    float4 s = {0.f, 0.f, 0.f, 0.f};
    float4 m = {-1e30f, -1e30f, -1e30f, -1e30f};
    int c0 = grp << 6;
#pragma unroll 4
    for (int k = 0; k < 64; k++) {
        float a = att[c0 + k];
        float4 v = *reinterpret_cast<const float4*>(xb + ((size_t)(c0 + k) << 12));
        v.x *= a; v.y *= a; v.z *= a; v.w *= a;
        s.x += v.x; s.y += v.y; s.z += v.z; s.w += v.w;
        m.x = fmaxf(m.x, v.x); m.y = fmaxf(m.y, v.y);
        m.z = fmaxf(m.z, v.z); m.w = fmaxf(m.w, v.w);
    }
    ssum[t] = s; smx[t] = m; __syncthreads();
    if (grp == 0) {
        float4 a0 = ssum[pq], a1 = ssum[pq + 64], a2 = ssum[pq + 128], a3 = ssum[pq + 192];
        float4 m0 = smx[pq],  m1 = smx[pq + 64],  m2 = smx[pq + 128],  m3 = smx[pq + 192];
        float4 ts, tm;
        ts.x = (a0.x + a1.x + a2.x + a3.x) * (1.f / 256.f);
        ts.y = (a0.y + a1.y + a2.y + a3.y) * (1.f / 256.f);
        ts.z = (a0.z + a1.z + a2.z + a3.z) * (1.f / 256.f);
        ts.w = (a0.w + a1.w + a2.w + a3.w) * (1.f / 256.f);
        tm.x = fmaxf(fmaxf(m0.x, m1.x), fmaxf(m2.x, m3.x));
        tm.y = fmaxf(fmaxf(m0.y, m1.y), fmaxf(m2.y, m3.y));
        tm.z = fmaxf(fmaxf(m0.z, m1.z), fmaxf(m2.z, m3.z));
        tm.w = fmaxf(fmaxf(m0.w, m1.w), fmaxf(m2.w, m3.w));
        *reinterpret_cast<float4*>(&g_sp_avg[(b << 12) + p0]) = ts;
        *reinterpret_cast<float4*>(&g_sp_max[(b << 12) + p0]) = tm;
    }
}

// K4: 7x7 conv over [avg_s, max_s] with zero padding, then sigmoid.
// Grid (NB, 16): one block per 4-row tile; one output pixel per thread.
__global__ void k_conv(const float* __restrict__ w_sp) {
    int b = blockIdx.x, tile = blockIdx.y;
    int y0 = tile * 4;
    int t = threadIdx.x;
    __shared__ float sa[10][64], sx[10][64], w[98];
    if (t < 98) w[t] = w_sp[t];
    for (int i = t; i < 640; i += 256) {
        int r = i >> 6, cx = i & 63;
        int gy = y0 + r - 3;
        float va = 0.f, vm = 0.f;
        if ((unsigned)gy < 64u) {
            va = g_sp_avg[b * 4096 + gy * 64 + cx];
            vm = g_sp_max[b * 4096 + gy * 64 + cx];
        }
        sa[r][cx] = va; sx[r][cx] = vm;
    }
    __syncthreads();
    int r = t >> 6, cx = t & 63;
    float acc = 0.f;
#pragma unroll
    for (int ky = 0; ky < 7; ky++) {
#pragma unroll
        for (int kx = 0; kx < 7; kx++) {
            int ix = cx + kx - 3;
            if ((unsigned)ix < 64u) {
                acc += w[ky * 7 + kx] * sa[r + ky][ix]
                     + w[49 + ky * 7 + kx] * sx[r + ky][ix];
            }
        }
    }
    g_s_att[b * 4096 + (y0 + r) * 64 + cx] = 1.f / (1.f + expf(-acc));
}

// K5: out = x * ch_att[b,c] * s_att[b,p]  (final answer when gamma==0)
__global__ void k_apply(const float* __restrict__ x, float* __restrict__ out) {
    int i4 = blockIdx.x * 256 + threadIdx.x;   // 1,048,576 float4s
    int e  = i4 << 2;
    int b  = e >> 20, c = (e >> 12) & 255, p = e & 4095;
    float a = g_ch_att[(b << 8) + c];
    float4 sv = *reinterpret_cast<const float4*>(&g_s_att[(b << 12) + p]);
    float4 xv = *reinterpret_cast<const float4*>(x + e);
    float4 o;
    o.x = xv.x * a * sv.x; o.y = xv.y * a * sv.y;
    o.z = xv.z * a * sv.z; o.w = xv.w * a * sv.w;
    *reinterpret_cast<float4*>(out + e) = o;
}

// ---- gamma != 0 path (exact; never runs in this bench since gamma == 0) ----

// K6: q/k/v 1x1-conv projections of x2 (= out buffer)
__global__ void k_proj(const float* __restrict__ x2,
                       const float* __restrict__ wq, const float* __restrict__ bq,
                       const float* __restrict__ wk, const float* __restrict__ bk,
                       const float* __restrict__ wv, const float* __restrict__ bv,
                       const float* __restrict__ gamma) {
    if (gamma[0] == 0.f) return;
    int chunk = blockIdx.x, b = blockIdx.y, t = threadIdx.x;
    __shared__ float xs[256 * 32];
    {
        const float* src = x2 + ((size_t)(b * 256 + t)) * HW + chunk * 32;
        for (int p = 0; p < 32; p += 4) {
            float4 v = *reinterpret_cast<const float4*>(src + p);
            xs[t * 32 + p] = v.x; xs[t * 32 + p + 1] = v.y;
            xs[t * 32 + p + 2] = v.z; xs[t * 32 + p + 3] = v.w;
        }
    }
    __syncthreads();
    for (int k = 0; k < 40; k++) {           // 320 outputs * 32 pixels / 256 threads
        int oi = k * 256 + t;
        int o = oi >> 5, p = oi & 31;
        const float* wr; float bias; float* dst; int row;
        if (o < 32)      { wr = wq + o * 256;        bias = bq[o];      dst = g_q; row = b * 32 + o; }
        else if (o < 64) { int r = o - 32; wr = wk + r * 256; bias = bk[r]; dst = g_k; row = b * 32 + r; }
        else             { int r = o - 64; wr = wv + r * 256; bias = bv[r]; dst = g_v; row = b * 256 + r; }
        float acc = bias;
        for (int c = 0; c < 256; c++) acc += wr[c] * xs[c * 32 + p];
        dst[(size_t)row * HW + chunk * 32 + p] = acc;
    }
}

// K7: one block per (b, query i): softmax over j, out[b,c,i] += g * sum_j p_j v[c,j]
__global__ void k_attn(float* __restrict__ out, const float* __restrict__ gamma) {
    float g = gamma[0];
    if (g == 0.f) return;
    int bi = blockIdx.x;
    int b = bi >> 12, i = bi & 4095;
    int t = threadIdx.x;
    __shared__ float qv[32];
    __shared__ float sbuf[4096];
    __shared__ float red[256];
    if (t < 32) qv[t] = g_q[(b * 32 + t) * HW + i];
    __syncthreads();
    float lm = -1e30f;
    for (int j = t; j < 4096; j += 256) {
        float s = 0.f;
#pragma unroll
        for (int d = 0; d < 32; d++) s += qv[d] * g_k[(b * 32 + d) * HW + j];
        sbuf[j] = s; lm = fmaxf(lm, s);
    }
    red[t] = lm; __syncthreads();
    for (int o = 128; o > 0; o >>= 1) {
        if (t < o) red[t] = fmaxf(red[t], red[t + o]);
        __syncthreads();
    }
    float m = red[0]; __syncthreads();
    float ls = 0.f;
    for (int j = t; j < 4096; j += 256) {
        float e = expf(sbuf[j] - m);
        sbuf[j] = e; ls += e;
    }
    red[t] = ls; __syncthreads();
    for (int o = 128; o > 0; o >>= 1) {
        if (t < o) red[t] += red[t + o];
        __syncthreads();
    }
    float inv = 1.f / red[0]; __syncthreads();
    float acc = 0.f;
    const float* vr = g_v + (size_t)(b * 256 + t) * HW;
    for (int j = 0; j < 4096; j++) acc += vr[j] * sbuf[j];
    out[(b * 256 + t) * HW + i] += g * acc * inv;
}

extern "C" void kernel_launch(void* const* d_in, const int* in_sizes, int n_in,
                              void* d_out, int out_size) {
    const float* x     = (const float*)d_in[0];
    const float* w1    = (const float*)d_in[1];
    const float* w2    = (const float*)d_in[2];
    const float* w_sp  = (const float*)d_in[3];
    const float* wq    = (const float*)d_in[4];
    const float* bq    = (const float*)d_in[5];
    const float* wk    = (const float*)d_in[6];
    const float* bk    = (const float*)d_in[7];
    const float* wv    = (const float*)d_in[8];
    const float* bv    = (const float*)d_in[9];
    const float* gamma = (const float*)d_in[10];
    float* out = (float*)d_out;

    k_chstats<<<NB * NC, 256>>>(x);
    k_mlp<<<NB, 256>>>(w1, w2);
    k_spstats<<<64, 256>>>(x);
    k_conv<<<dim3(NB, 16), 256>>>(w_sp);
    k_apply<<<NB * NC * HW / 1024, 256>>>(x, out);
    // gamma != 0 path: in-device early exit when gamma == 0 (exact identity)
    k_proj<<<dim3(HW / 32, NB), 256>>>(out, wq, bq, wk, bk, wv, bv, gamma);
    k_attn<<<NB * HW, 256>>>(out, gamma);
}

// round 5
// speedup vs baseline: 3.0487x; 1.6342x over previous
#include <cuda_runtime.h>
#include <math.h>

#define HW 4096
#define NC 256
#define NB 4

// ---- device scratch (16B-aligned: accessed via float4) ----
__device__ __align__(16) float g_ch_avg[NB*NC];
__device__ __align__(16) float g_ch_max[NB*NC];
__device__ __align__(16) float g_ch_att[NB*NC];
__device__ __align__(16) float g_sp_avg[NB*HW];
__device__ __align__(16) float g_sp_max[NB*HW];
// attention scratch (only used when gamma != 0; never in this bench)
__device__ __align__(16) float g_q[NB*32*HW];
__device__ __align__(16) float g_k[NB*32*HW];
__device__ __align__(16) float g_v[NB*NC*HW];

// K1: per-(b,c) spatial mean & max over 4096 pixels
__global__ void k_chstats(const float* __restrict__ x) {
    int bc = blockIdx.x;            // 0..1023
    int t  = threadIdx.x;           // 256
    const float4* xr = reinterpret_cast<const float4*>(x + (size_t)bc * HW);
    float s = 0.f, m = -1e30f;
#pragma unroll
    for (int i = 0; i < 4; i++) {
        float4 v = xr[t + i * 256];
        s += v.x + v.y + v.z + v.w;
        m = fmaxf(m, fmaxf(fmaxf(v.x, v.y), fmaxf(v.z, v.w)));
    }
    __shared__ float ss[256], sm[256];
    ss[t] = s; sm[t] = m; __syncthreads();
    for (int o = 128; o > 0; o >>= 1) {
        if (t < o) { ss[t] += ss[t + o]; sm[t] = fmaxf(sm[t], sm[t + o]); }
        __syncthreads();
    }
    if (t == 0) { g_ch_avg[bc] = ss[0] * (1.f / HW); g_ch_max[bc] = sm[0]; }
}

// K2: inline channel-MLP (redundant per block, trivial cost) + per-pixel channel
// mean/max of (x * ch_att). 256 blocks: b = blk>>6, 64 pixels per block.
__global__ void k_spstats(const float* __restrict__ x,
                          const float* __restrict__ w1, const float* __restrict__ w2) {
    int t   = threadIdx.x;
    int blk = blockIdx.x;
    int b   = blk >> 6;
    __shared__ float sa_[256], sx_[256], sh[16];
    __shared__ __align__(16) float att[256];
    __shared__ float4 ssum[256], smx[256];

    // ---- inline MLP: att = sigmoid(relu(avg@W1^T)@W2^T + relu(max@W1^T)@W2^T) ----
    sa_[t] = g_ch_avg[b * 256 + t];
    sx_[t] = g_ch_max[b * 256 + t];
    __syncthreads();
    {
        int wid = t >> 5, lid = t & 31;
#pragma unroll
        for (int u = 0; u < 2; u++) {
            int h = wid * 2 + u;
            const float* wr = w1 + h * 256;
            float ha = 0.f, hm = 0.f;
#pragma unroll
            for (int k = 0; k < 8; k++) {
                int c = k * 32 + lid;
                float wv = wr[c];
                ha += sa_[c] * wv; hm += sx_[c] * wv;
            }
#pragma unroll
            for (int o = 16; o > 0; o >>= 1) {
                ha += __shfl_down_sync(0xffffffff, ha, o);
                hm += __shfl_down_sync(0xffffffff, hm, o);
            }
            if (lid == 0) sh[h] = fmaxf(ha, 0.f) + fmaxf(hm, 0.f);
        }
    }
    __syncthreads();
    {
        float o = 0.f;
        const float* w2r = w2 + t * 16;
#pragma unroll
        for (int r = 0; r < 16; r++) o += sh[r] * w2r[r];
        att[t] = 1.f / (1.f + expf(-o));
        if ((blk & 63) == 0) g_ch_att[b * 256 + t] = att[t];  // publish (same value from each writer)
    }
    __syncthreads();

    // ---- per-pixel stats ----
    int pq = t & 15, cgrp = t >> 4;
    int p0 = (blk & 63) * 64 + pq * 4;
    int c0 = cgrp * 16;
    const float* xb = x + ((size_t)b << 20) + p0;
    float4 s = {0.f, 0.f, 0.f, 0.f};
    float4 m = {-1e30f, -1e30f, -1e30f, -1e30f};
#pragma unroll
    for (int k = 0; k < 16; k++) {
        float a = att[c0 + k];
        float4 v = *reinterpret_cast<const float4*>(xb + ((size_t)(c0 + k) << 12));
        v.x *= a; v.y *= a; v.z *= a; v.w *= a;
        s.x += v.x; s.y += v.y; s.z += v.z; s.w += v.w;
        m.x = fmaxf(m.x, v.x); m.y = fmaxf(m.y, v.y);
        m.z = fmaxf(m.z, v.z); m.w = fmaxf(m.w, v.w);
    }
    ssum[t] = s; smx[t] = m; __syncthreads();
    if (t < 16) {
        float4 ts = {0.f, 0.f, 0.f, 0.f};
        float4 tm = {-1e30f, -1e30f, -1e30f, -1e30f};
#pragma unroll
        for (int g = 0; g < 16; g++) {
            float4 a = ssum[g * 16 + t], q = smx[g * 16 + t];
            ts.x += a.x; ts.y += a.y; ts.z += a.z; ts.w += a.w;
            tm.x = fmaxf(tm.x, q.x); tm.y = fmaxf(tm.y, q.y);
            tm.z = fmaxf(tm.z, q.z); tm.w = fmaxf(tm.w, q.w);
        }
        ts.x *= (1.f / 256.f); ts.y *= (1.f / 256.f);
        ts.z *= (1.f / 256.f); ts.w *= (1.f / 256.f);
        int p = (blk & 63) * 64 + t * 4;
        *reinterpret_cast<float4*>(&g_sp_avg[(b << 12) + p]) = ts;
        *reinterpret_cast<float4*>(&g_sp_max[(b << 12) + p]) = tm;
    }
}

// K3: fused 7x7 conv (+sigmoid) and final apply.
// Grid (4, 16, 4): batch x 4-row-tile x 64-channel-group. 256 threads.
__global__ void k_convapply(const float* __restrict__ x, const float* __restrict__ w_sp,
                            float* __restrict__ out) {
    int b = blockIdx.x, tile = blockIdx.y, cg = blockIdx.z;
    int t = threadIdx.x;
    __shared__ __align__(16) float satt[256];
    __shared__ float w[98], sa[10][64], sx[10][64], catt[64];
    if (t < 98) w[t] = w_sp[t];
    if (t >= 128 && t < 192) catt[t - 128] = g_ch_att[b * 256 + cg * 64 + (t - 128)];
    for (int i = t; i < 640; i += 256) {
        int r = i >> 6, cx = i & 63;
        int gy = tile * 4 + r - 3;
        float va = 0.f, vm = 0.f;
        if ((unsigned)gy < 64u) {
            va = g_sp_avg[b * 4096 + gy * 64 + cx];
            vm = g_sp_max[b * 4096 + gy * 64 + cx];
        }
        sa[r][cx] = va; sx[r][cx] = vm;
    }
    __syncthreads();
    {
        int r = t >> 6, cx = t & 63;
        float acc = 0.f;
#pragma unroll
        for (int ky = 0; ky < 7; ky++) {
#pragma unroll
            for (int kx = 0; kx < 7; kx++) {
                int ix = cx + kx - 3;
                if ((unsigned)ix < 64u) {
                    acc += w[ky * 7 + kx] * sa[r + ky][ix]
                         + w[49 + ky * 7 + kx] * sx[r + ky][ix];
                }
            }
        }
        satt[t] = 1.f / (1.f + expf(-acc));
    }
    __syncthreads();
    // apply: 64 channels x 256 pixels (contiguous pixel range tile*256..+256)
    const float* xb = x   + ((size_t)b << 20) + ((size_t)cg << 18) + tile * 256;
    float*       ob = out + ((size_t)b << 20) + ((size_t)cg << 18) + tile * 256;
#pragma unroll
    for (int k = 0; k < 16; k++) {
        int idx = k * 256 + t;
        int cl = idx >> 6, pquad = idx & 63;
        float a = catt[cl];
        float4 sv = *reinterpret_cast<const float4*>(&satt[pquad * 4]);
        float4 xv = *reinterpret_cast<const float4*>(xb + ((size_t)cl << 12) + pquad * 4);
        float4 o;
        o.x = xv.x * a * sv.x; o.y = xv.y * a * sv.y;
        o.z = xv.z * a * sv.z; o.w = xv.w * a * sv.w;
        *reinterpret_cast<float4*>(ob + ((size_t)cl << 12) + pquad * 4) = o;
    }
}

// ---- gamma != 0 path (exact; never runs in this bench since gamma == 0) ----

// K4: q/k/v 1x1-conv projections of x2 (= out buffer). Persistent: 64 blocks.
__global__ void k_proj(const float* __restrict__ x2,
                       const float* __restrict__ wq, const float* __restrict__ bq,
                       const float* __restrict__ wk, const float* __restrict__ bk,
                       const float* __restrict__ wv, const float* __restrict__ bv,
                       const float* __restrict__ gamma) {
    if (gamma[0] == 0.f) return;
    int t = threadIdx.x;
    __shared__ __align__(16) float xs[256 * 32];
    for (int wkid = blockIdx.x; wkid < 128 * NB; wkid += gridDim.x) {
        int chunk = wkid & 127, b = wkid >> 7;
        __syncthreads();
        {
            const float* src = x2 + ((size_t)(b * 256 + t)) * HW + chunk * 32;
            for (int p = 0; p < 32; p += 4) {
                float4 v = *reinterpret_cast<const float4*>(src + p);
                xs[t * 32 + p] = v.x; xs[t * 32 + p + 1] = v.y;
                xs[t * 32 + p + 2] = v.z; xs[t * 32 + p + 3] = v.w;
            }
        }
        __syncthreads();
        for (int k = 0; k < 40; k++) {           // 320 outputs * 32 pixels / 256 threads
            int oi = k * 256 + t;
            int o = oi >> 5, p = oi & 31;
            const float* wr; float bias; float* dst; int row;
            if (o < 32)      { wr = wq + o * 256;        bias = bq[o];      dst = g_q; row = b * 32 + o; }
            else if (o < 64) { int r = o - 32; wr = wk + r * 256; bias = bk[r]; dst = g_k; row = b * 32 + r; }
            else             { int r = o - 64; wr = wv + r * 256; bias = bv[r]; dst = g_v; row = b * 256 + r; }
            float acc = bias;
            for (int c = 0; c < 256; c++) acc += wr[c] * xs[c * 32 + p];
            dst[(size_t)row * HW + chunk * 32 + p] = acc;
        }
    }
}

// K5: per (b, query i): softmax over j, out[b,c,i] += g * sum_j p_j v[c,j]. Persistent.
__global__ void k_attn(float* __restrict__ out, const float* __restrict__ gamma) {
    float g = gamma[0];
    if (g == 0.f) return;
    int t = threadIdx.x;
    __shared__ float qv[32];
    __shared__ float sbuf[4096];
    __shared__ float red[256];
    for (int bi = blockIdx.x; bi < NB * HW; bi += gridDim.x) {
        int b = bi >> 12, i = bi & 4095;
        if (t < 32) qv[t] = g_q[(b * 32 + t) * HW + i];
        __syncthreads();
        float lm = -1e30f;
        for (int j = t; j < 4096; j += 256) {
            float s = 0.f;
#pragma unroll
            for (int d = 0; d < 32; d++) s += qv[d] * g_k[(b * 32 + d) * HW + j];
            sbuf[j] = s; lm = fmaxf(lm, s);
        }
        red[t] = lm; __syncthreads();
        for (int o = 128; o > 0; o >>= 1) {
            if (t < o) red[t] = fmaxf(red[t], red[t + o]);
            __syncthreads();
        }
        float m = red[0]; __syncthreads();
        float ls = 0.f;
        for (int j = t; j < 4096; j += 256) {
            float e = expf(sbuf[j] - m);
            sbuf[j] = e; ls += e;
        }
        red[t] = ls; __syncthreads();
        for (int o = 128; o > 0; o >>= 1) {
            if (t < o) red[t] += red[t + o];
            __syncthreads();
        }
        float inv = 1.f / red[0]; __syncthreads();
        float acc = 0.f;
        const float* vr = g_v + (size_t)(b * 256 + t) * HW;
        for (int j = 0; j < 4096; j++) acc += vr[j] * sbuf[j];
        out[(b * 256 + t) * HW + i] += g * acc * inv;
        __syncthreads();
    }
}

extern "C" void kernel_launch(void* const* d_in, const int* in_sizes, int n_in,
                              void* d_out, int out_size) {
    const float* x     = (const float*)d_in[0];
    const float* w1    = (const float*)d_in[1];
    const float* w2    = (const float*)d_in[2];
    const float* w_sp  = (const float*)d_in[3];
    const float* wq    = (const float*)d_in[4];
    const float* bq    = (const float*)d_in[5];
    const float* wk    = (const float*)d_in[6];
    const float* bk    = (const float*)d_in[7];
    const float* wv    = (const float*)d_in[8];
    const float* bv    = (const float*)d_in[9];
    const float* gamma = (const float*)d_in[10];
    float* out = (float*)d_out;

    k_chstats<<<NB * NC, 256>>>(x);
    k_spstats<<<256, 256>>>(x, w1, w2);
    k_convapply<<<dim3(NB, 16, 4), 256>>>(x, w_sp, out);
    // gamma != 0 path: in-device early exit when gamma == 0 (exact identity)
    k_proj<<<64, 256>>>(out, wq, bq, wk, bk, wv, bv, gamma);
    k_attn<<<256, 256>>>(out, gamma);
}